// round 9
// baseline (speedup 1.0000x reference)
#include <cuda_runtime.h>

// Problem constants: N=1, C=4, D=3, H=W=64
#define NELEM 49152      // 4*3*64*64
#define HW    4096
#define PERCH 12288      // D*H*W per channel

__device__ float  d_vpre[NELEM];
__device__ float  d_kqpre[NELEM];
__device__ float  d_part[16 * 48];     // [quant(4)*chan(4)][48 block partials]
__device__ float  d_v[NELEM];
__device__ float  d_q[NELEM];
__device__ float  d_qmax[12];

// sparsity-compacted state (per slice of 4096)
__device__ int    d_nnz[12];
__device__ int    d_P[12];             // nnz padded up to multiple of 64
__device__ float  d_qnz[NELEM];        // compacted q values (padding = 0)
__device__ int    d_idxnz[NELEM];      // compacted k -> original pos
__device__ int    d_rank[NELEM];       // original pos -> compacted k (nz only)
__device__ float  d_S0[12];            // sum_{zero i} v_i / 4096
__device__ float  d_AnzP[12][8];       // per-chunk Anz partials
__device__ float2 d_qanz[NELEM];       // compacted {qln_i, a_i} (padding = {0,0})
__device__ float  d_ppart[8 * NELEM];  // pass2 chunk partials (compacted idx)

__device__ __forceinline__ float ex2f_(float x) {
    float y;
    asm("ex2.approx.f32 %0, %1;" : "=f"(y) : "f"(x));
    return y;
}

#define L2E 1.4426950408889634f

// ---------------------------------------------------------------------------
// K1: conv3x3x3 + bias and conv1x1x1 + bias; per-block stats partials
// ---------------------------------------------------------------------------
__global__ void k_conv(const float* __restrict__ x, const float* __restrict__ W3,
                       const float* __restrict__ b3, const float* __restrict__ W1,
                       const float* __restrict__ b1)
{
    __shared__ float sW3[432], sW1[16], sb3[4], sb1[4];
    int t = threadIdx.x;
    for (int i = t; i < 432; i += 256) sW3[i] = W3[i];
    if (t < 16)  sW1[t] = W1[t];
    if (t < 4) { sb3[t] = b3[t]; sb1[t] = b1[t]; }
    __syncthreads();

    int idx = blockIdx.x * 256 + t;
    int o  = idx / PERCH;
    int r  = idx % PERCH;
    int d  = r >> 12;
    int hw = r & 4095;
    int h  = hw >> 6;
    int w  = hw & 63;

    float acc3 = sb3[o], acc1 = sb1[o];
    #pragma unroll
    for (int i = 0; i < 4; i++) {
        const float* xi = x + i * PERCH;
        acc1 = fmaf(xi[(d << 12) + hw], sW1[o * 4 + i], acc1);
        const float* wk = sW3 + (o * 4 + i) * 27;
        #pragma unroll
        for (int kd = 0; kd < 3; kd++) {
            int zd = d + kd - 1;
            if (zd < 0 || zd > 2) continue;
            #pragma unroll
            for (int kh = 0; kh < 3; kh++) {
                int zh = h + kh - 1;
                if ((unsigned)zh > 63u) continue;
                #pragma unroll
                for (int kw = 0; kw < 3; kw++) {
                    int zw = w + kw - 1;
                    if ((unsigned)zw > 63u) continue;
                    acc3 = fmaf(xi[(zd << 12) + (zh << 6) + zw],
                                wk[kd * 9 + kh * 3 + kw], acc3);
                }
            }
        }
    }
    d_vpre[idx]  = acc3;
    d_kqpre[idx] = acc1;

    float v0 = acc3, v1 = acc3 * acc3, v2 = acc1, v3 = acc1 * acc1;
    #pragma unroll
    for (int off = 16; off; off >>= 1) {
        v0 += __shfl_down_sync(0xffffffffu, v0, off);
        v1 += __shfl_down_sync(0xffffffffu, v1, off);
        v2 += __shfl_down_sync(0xffffffffu, v2, off);
        v3 += __shfl_down_sync(0xffffffffu, v3, off);
    }
    __shared__ float sred[8][4];
    int wid = t >> 5, lane = t & 31;
    if (lane == 0) { sred[wid][0] = v0; sred[wid][1] = v1; sred[wid][2] = v2; sred[wid][3] = v3; }
    __syncthreads();
    if (t == 0) {
        float s0 = 0, s1 = 0, s2 = 0, s3 = 0;
        #pragma unroll
        for (int i = 0; i < 8; i++) { s0 += sred[i][0]; s1 += sred[i][1]; s2 += sred[i][2]; s3 += sred[i][3]; }
        int b2 = blockIdx.x % 48;
        d_part[(0 * 4 + o) * 48 + b2] = s0;
        d_part[(1 * 4 + o) * 48 + b2] = s1;
        d_part[(2 * 4 + o) * 48 + b2] = s2;
        d_part[(3 * 4 + o) * 48 + b2] = s3;
    }
}

// ---------------------------------------------------------------------------
// K2: fused stats + BN/ReLU + qmax + compaction. grid 12 x 1024 (block=slice)
// ---------------------------------------------------------------------------
__global__ void k_prep(const float* __restrict__ g3, const float* __restrict__ be3,
                       const float* __restrict__ g1, const float* __restrict__ be1)
{
    __shared__ float scoef[4];            // {sc3, sh3, sc1, sh1} for this channel
    __shared__ float ssum[4];
    __shared__ int   soff[32];
    __shared__ float sv[32];
    __shared__ float smax[32];
    __shared__ int   s_nnz, s_P;

    int s = blockIdx.x, t = threadIdx.x;
    int lane = t & 31, w = t >> 5;
    int c = s / 3;                        // channel
    int sb = s * 4096;

    // BN stats: threads 0..3 each reduce 48 partials for quantity q of channel c
    if (t < 4) {
        const float* p = d_part + (t * 4 + c) * 48;
        float a = 0.f;
        #pragma unroll
        for (int i = 0; i < 48; i++) a += p[i];
        ssum[t] = a;
    }
    __syncthreads();
    if (t == 0) {
        const float inv_n = 1.0f / 12288.0f;
        float m3  = ssum[0] * inv_n;
        float vr3 = ssum[1] * inv_n - m3 * m3;
        float sc3 = g3[c] * rsqrtf(vr3 + 1e-5f);
        float m1  = ssum[2] * inv_n;
        float vr1 = ssum[3] * inv_n - m1 * m1;
        float sc1 = g1[c] * rsqrtf(vr1 + 1e-5f);
        scoef[0] = sc3; scoef[1] = be3[c] - m3 * sc3;
        scoef[2] = sc1; scoef[3] = be1[c] - m1 * sc1;
        if (s == 0) {   // zero-init of Anz partials (pass2 overwrites when nnz>0)
            #pragma unroll
            for (int i = 0; i < 12; i++)
                #pragma unroll
                for (int jj = 0; jj < 8; jj++) d_AnzP[i][jj] = 0.f;
        }
    }
    __syncthreads();
    float sc3 = scoef[0], sh3 = scoef[1], sc1 = scoef[2], sh1 = scoef[3];

    // BN + ReLU on 4 consecutive elements
    int pos = t * 4;
    float4 pre3 = *(const float4*)(d_vpre  + sb + pos);
    float4 pre1 = *(const float4*)(d_kqpre + sb + pos);
    float4 vv, qv;
    vv.x = fmaxf(fmaf(pre3.x, sc3, sh3), 0.f);
    vv.y = fmaxf(fmaf(pre3.y, sc3, sh3), 0.f);
    vv.z = fmaxf(fmaf(pre3.z, sc3, sh3), 0.f);
    vv.w = fmaxf(fmaf(pre3.w, sc3, sh3), 0.f);
    qv.x = fmaxf(fmaf(pre1.x, sc1, sh1), 0.f);
    qv.y = fmaxf(fmaf(pre1.y, sc1, sh1), 0.f);
    qv.z = fmaxf(fmaf(pre1.z, sc1, sh1), 0.f);
    qv.w = fmaxf(fmaf(pre1.w, sc1, sh1), 0.f);
    *(float4*)(d_v + sb + pos) = vv;
    *(float4*)(d_q + sb + pos) = qv;

    // block qmax
    float m = fmaxf(fmaxf(qv.x, qv.y), fmaxf(qv.z, qv.w));
    #pragma unroll
    for (int off = 16; off; off >>= 1) m = fmaxf(m, __shfl_down_sync(0xffffffffu, m, off));
    if (lane == 0) smax[w] = m;

    // compaction flags + scans
    int c0 = qv.x > 0.f, c1 = qv.y > 0.f, c2 = qv.z > 0.f, c3 = qv.w > 0.f;
    int cnt = c0 + c1 + c2 + c3;
    float vz = (c0 ? 0.f : vv.x) + (c1 ? 0.f : vv.y)
             + (c2 ? 0.f : vv.z) + (c3 ? 0.f : vv.w);

    int inc = cnt;                        // warp inclusive scan
    #pragma unroll
    for (int off = 1; off < 32; off <<= 1) {
        int n = __shfl_up_sync(0xffffffffu, inc, off);
        if (lane >= off) inc += n;
    }
    float vzr = vz;                       // warp reduce zero-v sum
    #pragma unroll
    for (int off = 16; off; off >>= 1) vzr += __shfl_down_sync(0xffffffffu, vzr, off);
    if (lane == 31) soff[w] = inc;
    if (lane == 0)  sv[w]   = vzr;
    __syncthreads();
    if (t == 0) {                         // serial deterministic warp-offset scan
        int acc = 0; float vacc = 0.f; float mm = smax[0];
        #pragma unroll
        for (int i = 0; i < 32; i++) {
            int tmp = soff[i]; soff[i] = acc; acc += tmp;
            vacc += sv[i];
            mm = fmaxf(mm, smax[i]);
        }
        s_nnz = acc;
        s_P   = (acc + 63) & ~63;
        d_nnz[s]  = acc;
        d_P[s]    = s_P;
        d_S0[s]   = vacc * (1.0f / 4096.0f);
        d_qmax[s] = mm;
    }
    __syncthreads();
    int k = soff[w] + (inc - cnt);
    if (c0) { d_qnz[sb + k] = qv.x; d_idxnz[sb + k] = pos;     d_rank[sb + pos]     = k; k++; }
    if (c1) { d_qnz[sb + k] = qv.y; d_idxnz[sb + k] = pos + 1; d_rank[sb + pos + 1] = k; k++; }
    if (c2) { d_qnz[sb + k] = qv.z; d_idxnz[sb + k] = pos + 2; d_rank[sb + pos + 2] = k; k++; }
    if (c3) { d_qnz[sb + k] = qv.w; d_idxnz[sb + k] = pos + 3; d_rank[sb + pos + 3] = k; k++; }
    for (int i = s_nnz + t; i < s_P; i += 1024) {
        d_qnz[sb + i]  = 0.f;
        d_qanz[sb + i] = make_float2(0.f, 0.f);
    }
}

// ---------------------------------------------------------------------------
// K3: pass1, 2 rows/lane (64 rows/block), 8 warp-chunks. grid 768 x 256
// slice = blk>>6, rowgroup(64) = blk&63
// ---------------------------------------------------------------------------
__global__ void k_pass1()
{
    int s = blockIdx.x >> 6;
    int g = blockIdx.x & 63;
    int nnz = d_nnz[s];
    if (g * 64 >= nnz) return;
    __shared__ float sq[4096];
    __shared__ float partZ0[8][32];
    __shared__ float partZ1[8][32];
    __shared__ float s_qmax;
    int t = threadIdx.x, w = t >> 5, lane = t & 31;
    int sb = s << 12;
    int P  = d_P[s];
    int P4 = P >> 2;

    float4* sq4 = (float4*)sq;
    const float4* gq4 = (const float4*)(d_qnz + sb);
    for (int j = t; j < P4; j += 256) sq4[j] = gq4[j];
    if (t == 0) s_qmax = d_qmax[s];
    __syncthreads();

    int k0 = g * 64 + lane;
    int k1 = k0 + 32;
    float qi0 = (k0 < P) ? sq[k0] : 0.f;
    float qi1 = (k1 < P) ? sq[k1] : 0.f;
    float qln0 = qi0 * L2E, nm0 = -qln0 * s_qmax;
    float qln1 = qi1 * L2E, nm1 = -qln1 * s_qmax;

    int P32 = P >> 5;                      // float4s per warp chunk
    const float4* p4 = (const float4*)sq + w * P32;
    float z00 = 0, z01 = 0, z02 = 0, z03 = 0;
    float z10 = 0, z11 = 0, z12 = 0, z13 = 0;
    #pragma unroll 2
    for (int j4 = 0; j4 < P32; j4++) {
        float4 qq = p4[j4];                // warp-uniform broadcast
        z00 += ex2f_(fmaf(qln0, qq.x, nm0));
        z10 += ex2f_(fmaf(qln1, qq.x, nm1));
        z01 += ex2f_(fmaf(qln0, qq.y, nm0));
        z11 += ex2f_(fmaf(qln1, qq.y, nm1));
        z02 += ex2f_(fmaf(qln0, qq.z, nm0));
        z12 += ex2f_(fmaf(qln1, qq.z, nm1));
        z03 += ex2f_(fmaf(qln0, qq.w, nm0));
        z13 += ex2f_(fmaf(qln1, qq.w, nm1));
    }
    partZ0[w][lane] = (z00 + z01) + (z02 + z03);
    partZ1[w][lane] = (z10 + z11) + (z12 + z13);
    __syncthreads();
    if (w < 2) {
        int k = (w == 0) ? k0 : (k0 + 32);
        if (k < nnz) {
            float nm = (w == 0) ? nm0 : nm1;
            float ql = (w == 0) ? qln0 : qln1;
            float E = ex2f_(nm);
            float Zs;
            if (w == 0) {
                Zs = (((partZ0[0][lane] + partZ0[1][lane]) + (partZ0[2][lane] + partZ0[3][lane]))
                   +  ((partZ0[4][lane] + partZ0[5][lane]) + (partZ0[6][lane] + partZ0[7][lane])));
            } else {
                Zs = (((partZ1[0][lane] + partZ1[1][lane]) + (partZ1[2][lane] + partZ1[3][lane]))
                   +  ((partZ1[4][lane] + partZ1[5][lane]) + (partZ1[6][lane] + partZ1[7][lane])));
            }
            float Z = Zs + (float)(4096 - P) * E;
            int row = d_idxnz[sb + k];
            float av = d_v[sb + row] / Z * E;
            d_qanz[sb + k] = make_float2(ql, av);
        }
    }
}

// ---------------------------------------------------------------------------
// K4: pass2, 8 i-chunks, 2 rows/thread (256 rows/block). grid 1536 x 128
// slice = blk>>7; chunk = (blk&127)&7; rowgroup(256) = (blk&127)>>3
// ---------------------------------------------------------------------------
__global__ void k_pass2()
{
    int s   = blockIdx.x >> 7;
    int rem = blockIdx.x & 127;
    int c   = rem & 7;
    int g   = rem >> 3;
    int nnz = d_nnz[s];
    if (g * 256 >= nnz) return;
    int P  = d_P[s];
    int P8 = P >> 3;                       // entries per chunk (mult of 8)
    __shared__ float2 sqa[512];
    __shared__ float sanz[4];
    int t = threadIdx.x;
    int sb = s << 12;

    float4* s4 = (float4*)sqa;
    const float4* g4 = (const float4*)(d_qanz + sb + c * P8);
    int nf4 = P8 >> 1;                     // float4s in chunk (mult of 4)
    for (int j = t; j < nf4; j += 128) s4[j] = g4[j];
    __syncthreads();

    // Anz chunk partial (only g==0 blocks; data already in smem)
    if (g == 0) {
        int w = t >> 5, lane = t & 31;
        float a = 0.f;
        for (int i = t; i < P8; i += 128) a += sqa[i].y;
        #pragma unroll
        for (int off = 16; off; off >>= 1) a += __shfl_down_sync(0xffffffffu, a, off);
        if (lane == 0) sanz[w] = a;
    }

    int k0 = g * 256 + t;
    int k1 = k0 + 128;
    float qj0 = d_qnz[sb + ((k0 < nnz) ? k0 : 0)];
    float qj1 = d_qnz[sb + ((k1 < nnz) ? k1 : 0)];
    float a00 = 0, a01 = 0, a02 = 0, a03 = 0;
    float a10 = 0, a11 = 0, a12 = 0, a13 = 0;
    const float4* p4 = (const float4*)sqa;
    #pragma unroll 2
    for (int i4 = 0; i4 < nf4; i4 += 2) {
        float4 u  = p4[i4];                // {qln, a}, {qln, a}
        float4 ww = p4[i4 + 1];
        a00 = fmaf(u.y,  ex2f_(u.x  * qj0), a00);
        a10 = fmaf(u.y,  ex2f_(u.x  * qj1), a10);
        a01 = fmaf(u.w,  ex2f_(u.z  * qj0), a01);
        a11 = fmaf(u.w,  ex2f_(u.z  * qj1), a11);
        a02 = fmaf(ww.y, ex2f_(ww.x * qj0), a02);
        a12 = fmaf(ww.y, ex2f_(ww.x * qj1), a12);
        a03 = fmaf(ww.w, ex2f_(ww.z * qj0), a03);
        a13 = fmaf(ww.w, ex2f_(ww.z * qj1), a13);
    }
    if (k0 < nnz) d_ppart[c * NELEM + sb + k0] = (a00 + a01) + (a02 + a03);
    if (k1 < nnz) d_ppart[c * NELEM + sb + k1] = (a10 + a11) + (a12 + a13);

    if (g == 0) {
        __syncthreads();
        if (t == 0) d_AnzP[s][c] = (sanz[0] + sanz[1]) + (sanz[2] + sanz[3]);
    }
}

// ---------------------------------------------------------------------------
// K5: final — Datt inline + assemble Patt + residual. grid 64 x 256 over (c,hw)
// ---------------------------------------------------------------------------
__global__ void k_final(const float* __restrict__ x, const float* __restrict__ gama,
                        float* __restrict__ out)
{
    int tid = blockIdx.x * 256 + threadIdx.x;   // 0..16383
    int c = tid >> 12, hw = tid & 4095;
    int base = c * PERCH + hw;
    float gm = gama[0];

    float q0 = d_q[base], q1 = d_q[base + HW], q2 = d_q[base + 2 * HW];
    float v0 = d_v[base], v1 = d_v[base + HW], v2 = d_v[base + 2 * HW];

    // depth attention
    float qm = fmaxf(q0, fmaxf(q1, q2));
    float o0 = 0, o1 = 0, o2 = 0;
    {
        float ql = q0 * L2E, nm = -ql * qm;
        float e0 = ex2f_(fmaf(ql, q0, nm)), e1 = ex2f_(fmaf(ql, q1, nm)), e2 = ex2f_(fmaf(ql, q2, nm));
        float w_ = v0 / (e0 + e1 + e2);
        o0 = fmaf(w_, e0, o0); o1 = fmaf(w_, e1, o1); o2 = fmaf(w_, e2, o2);
    }
    {
        float ql = q1 * L2E, nm = -ql * qm;
        float e0 = ex2f_(fmaf(ql, q0, nm)), e1 = ex2f_(fmaf(ql, q1, nm)), e2 = ex2f_(fmaf(ql, q2, nm));
        float w_ = v1 / (e0 + e1 + e2);
        o0 = fmaf(w_, e0, o0); o1 = fmaf(w_, e1, o1); o2 = fmaf(w_, e2, o2);
    }
    {
        float ql = q2 * L2E, nm = -ql * qm;
        float e0 = ex2f_(fmaf(ql, q0, nm)), e1 = ex2f_(fmaf(ql, q1, nm)), e2 = ex2f_(fmaf(ql, q2, nm));
        float w_ = v2 / (e0 + e1 + e2);
        o0 = fmaf(w_, e0, o0); o1 = fmaf(w_, e1, o1); o2 = fmaf(w_, e2, o2);
    }

    float dat[3] = {o0, o1, o2};
    float qd[3]  = {q0, q1, q2};
    #pragma unroll
    for (int d = 0; d < 3; d++) {
        int s = c * 3 + d;
        int idx = base + d * HW;
        float patt;
        if (qd[d] > 0.f) {
            int b = (s << 12) + d_rank[idx];
            patt = (((d_ppart[b] + d_ppart[NELEM + b])
                  +  (d_ppart[2 * NELEM + b] + d_ppart[3 * NELEM + b]))
                  + ((d_ppart[4 * NELEM + b] + d_ppart[5 * NELEM + b])
                  +  (d_ppart[6 * NELEM + b] + d_ppart[7 * NELEM + b])));
        } else {
            patt = (((d_AnzP[s][0] + d_AnzP[s][1]) + (d_AnzP[s][2] + d_AnzP[s][3]))
                  + ((d_AnzP[s][4] + d_AnzP[s][5]) + (d_AnzP[s][6] + d_AnzP[s][7])));
        }
        patt += d_S0[s];
        out[idx] = fmaf(gm, patt + dat[d], x[idx]);
    }
}

// ---------------------------------------------------------------------------
extern "C" void kernel_launch(void* const* d_in, const int* in_sizes, int n_in,
                              void* d_out, int out_size)
{
    const float* x    = (const float*)d_in[0];
    const float* W3   = (const float*)d_in[1];
    const float* b3   = (const float*)d_in[2];
    const float* g3   = (const float*)d_in[3];
    const float* be3  = (const float*)d_in[4];
    const float* W1   = (const float*)d_in[5];
    const float* b1   = (const float*)d_in[6];
    const float* g1   = (const float*)d_in[7];
    const float* be1  = (const float*)d_in[8];
    const float* gama = (const float*)d_in[9];
    float* out = (float*)d_out;

    k_conv <<<192,  256>>>(x, W3, b3, W1, b1);
    k_prep <<<12,  1024>>>(g3, be3, g1, be1);
    k_pass1<<<768,  256>>>();
    k_pass2<<<1536, 128>>>();
    k_final<<<64,   256>>>(x, gama, out);
}

// round 10
// speedup vs baseline: 1.1110x; 1.1110x over previous
#include <cuda_runtime.h>

// Problem constants: N=1, C=4, D=3, H=W=64
#define NELEM 49152      // 4*3*64*64
#define HW    4096
#define PERCH 12288      // D*H*W per channel

__device__ float  d_vpre[NELEM];
__device__ float  d_kqpre[NELEM];
__device__ float  d_part[16 * 48];     // [quant(4)*chan(4)][48 block partials]
__device__ float  d_v[NELEM];
__device__ float  d_q[NELEM];
__device__ float  d_qmax[12];

// sparsity-compacted state (per slice of 4096)
__device__ int    d_nnz[12];
__device__ int    d_P[12];             // nnz padded up to multiple of 64
__device__ float  d_qnz[NELEM];        // compacted q values (padding = 0)
__device__ int    d_idxnz[NELEM];      // compacted k -> original pos
__device__ int    d_rank[NELEM];       // original pos -> compacted k (nz only)
__device__ float  d_S0[12];            // sum_{zero i} v_i / 4096
__device__ float  d_AnzP[12][16];      // per-chunk Anz partials
__device__ float2 d_qanz[NELEM];       // compacted {qln_i, a_i} (padding = {0,0})
__device__ float  d_ppart[16 * NELEM]; // pass2 chunk partials (compacted idx)

__device__ __forceinline__ float ex2f_(float x) {
    float y;
    asm("ex2.approx.f32 %0, %1;" : "=f"(y) : "f"(x));
    return y;
}

#define L2E 1.4426950408889634f

// ---------------------------------------------------------------------------
// K1: conv3x3x3 + bias and conv1x1x1 + bias; per-block stats partials
// ---------------------------------------------------------------------------
__global__ void k_conv(const float* __restrict__ x, const float* __restrict__ W3,
                       const float* __restrict__ b3, const float* __restrict__ W1,
                       const float* __restrict__ b1)
{
    __shared__ float sW3[432], sW1[16], sb3[4], sb1[4];
    int t = threadIdx.x;
    for (int i = t; i < 432; i += 256) sW3[i] = W3[i];
    if (t < 16)  sW1[t] = W1[t];
    if (t < 4) { sb3[t] = b3[t]; sb1[t] = b1[t]; }
    __syncthreads();

    int idx = blockIdx.x * 256 + t;
    int o  = idx / PERCH;
    int r  = idx % PERCH;
    int d  = r >> 12;
    int hw = r & 4095;
    int h  = hw >> 6;
    int w  = hw & 63;

    float acc3 = sb3[o], acc1 = sb1[o];
    #pragma unroll
    for (int i = 0; i < 4; i++) {
        const float* xi = x + i * PERCH;
        acc1 = fmaf(xi[(d << 12) + hw], sW1[o * 4 + i], acc1);
        const float* wk = sW3 + (o * 4 + i) * 27;
        #pragma unroll
        for (int kd = 0; kd < 3; kd++) {
            int zd = d + kd - 1;
            if (zd < 0 || zd > 2) continue;
            #pragma unroll
            for (int kh = 0; kh < 3; kh++) {
                int zh = h + kh - 1;
                if ((unsigned)zh > 63u) continue;
                #pragma unroll
                for (int kw = 0; kw < 3; kw++) {
                    int zw = w + kw - 1;
                    if ((unsigned)zw > 63u) continue;
                    acc3 = fmaf(xi[(zd << 12) + (zh << 6) + zw],
                                wk[kd * 9 + kh * 3 + kw], acc3);
                }
            }
        }
    }
    d_vpre[idx]  = acc3;
    d_kqpre[idx] = acc1;

    float v0 = acc3, v1 = acc3 * acc3, v2 = acc1, v3 = acc1 * acc1;
    #pragma unroll
    for (int off = 16; off; off >>= 1) {
        v0 += __shfl_down_sync(0xffffffffu, v0, off);
        v1 += __shfl_down_sync(0xffffffffu, v1, off);
        v2 += __shfl_down_sync(0xffffffffu, v2, off);
        v3 += __shfl_down_sync(0xffffffffu, v3, off);
    }
    __shared__ float sred[8][4];
    int wid = t >> 5, lane = t & 31;
    if (lane == 0) { sred[wid][0] = v0; sred[wid][1] = v1; sred[wid][2] = v2; sred[wid][3] = v3; }
    __syncthreads();
    if (t == 0) {
        float s0 = 0, s1 = 0, s2 = 0, s3 = 0;
        #pragma unroll
        for (int i = 0; i < 8; i++) { s0 += sred[i][0]; s1 += sred[i][1]; s2 += sred[i][2]; s3 += sred[i][3]; }
        int b2 = blockIdx.x % 48;
        d_part[(0 * 4 + o) * 48 + b2] = s0;
        d_part[(1 * 4 + o) * 48 + b2] = s1;
        d_part[(2 * 4 + o) * 48 + b2] = s2;
        d_part[(3 * 4 + o) * 48 + b2] = s3;
    }
}

// ---------------------------------------------------------------------------
// K2: fused stats + BN/ReLU + qmax + compaction. grid 12 x 1024 (block=slice)
// ---------------------------------------------------------------------------
__global__ void k_prep(const float* __restrict__ g3, const float* __restrict__ be3,
                       const float* __restrict__ g1, const float* __restrict__ be1)
{
    __shared__ float scoef[4];            // {sc3, sh3, sc1, sh1} for this channel
    __shared__ float ssum[4];
    __shared__ int   soff[32];
    __shared__ float sv[32];
    __shared__ float smax[32];
    __shared__ int   s_nnz, s_P;

    int s = blockIdx.x, t = threadIdx.x;
    int lane = t & 31, w = t >> 5;
    int c = s / 3;                        // channel
    int sb = s * 4096;

    // BN stats: threads 0..3 each reduce 48 partials for quantity q of channel c
    if (t < 4) {
        const float* p = d_part + (t * 4 + c) * 48;
        float a = 0.f;
        #pragma unroll
        for (int i = 0; i < 48; i++) a += p[i];
        ssum[t] = a;
    }
    __syncthreads();
    if (t == 0) {
        const float inv_n = 1.0f / 12288.0f;
        float m3  = ssum[0] * inv_n;
        float vr3 = ssum[1] * inv_n - m3 * m3;
        float sc3 = g3[c] * rsqrtf(vr3 + 1e-5f);
        float m1  = ssum[2] * inv_n;
        float vr1 = ssum[3] * inv_n - m1 * m1;
        float sc1 = g1[c] * rsqrtf(vr1 + 1e-5f);
        scoef[0] = sc3; scoef[1] = be3[c] - m3 * sc3;
        scoef[2] = sc1; scoef[3] = be1[c] - m1 * sc1;
        if (s == 0) {   // zero-init of Anz partials (pass2 overwrites when nnz>0)
            #pragma unroll
            for (int i = 0; i < 12; i++)
                #pragma unroll
                for (int jj = 0; jj < 16; jj++) d_AnzP[i][jj] = 0.f;
        }
    }
    __syncthreads();
    float sc3 = scoef[0], sh3 = scoef[1], sc1 = scoef[2], sh1 = scoef[3];

    // BN + ReLU on 4 consecutive elements
    int pos = t * 4;
    float4 pre3 = *(const float4*)(d_vpre  + sb + pos);
    float4 pre1 = *(const float4*)(d_kqpre + sb + pos);
    float4 vv, qv;
    vv.x = fmaxf(fmaf(pre3.x, sc3, sh3), 0.f);
    vv.y = fmaxf(fmaf(pre3.y, sc3, sh3), 0.f);
    vv.z = fmaxf(fmaf(pre3.z, sc3, sh3), 0.f);
    vv.w = fmaxf(fmaf(pre3.w, sc3, sh3), 0.f);
    qv.x = fmaxf(fmaf(pre1.x, sc1, sh1), 0.f);
    qv.y = fmaxf(fmaf(pre1.y, sc1, sh1), 0.f);
    qv.z = fmaxf(fmaf(pre1.z, sc1, sh1), 0.f);
    qv.w = fmaxf(fmaf(pre1.w, sc1, sh1), 0.f);
    *(float4*)(d_v + sb + pos) = vv;
    *(float4*)(d_q + sb + pos) = qv;

    // block qmax
    float m = fmaxf(fmaxf(qv.x, qv.y), fmaxf(qv.z, qv.w));
    #pragma unroll
    for (int off = 16; off; off >>= 1) m = fmaxf(m, __shfl_down_sync(0xffffffffu, m, off));
    if (lane == 0) smax[w] = m;

    // compaction flags + scans
    int c0 = qv.x > 0.f, c1 = qv.y > 0.f, c2 = qv.z > 0.f, c3 = qv.w > 0.f;
    int cnt = c0 + c1 + c2 + c3;
    float vz = (c0 ? 0.f : vv.x) + (c1 ? 0.f : vv.y)
             + (c2 ? 0.f : vv.z) + (c3 ? 0.f : vv.w);

    int inc = cnt;                        // warp inclusive scan
    #pragma unroll
    for (int off = 1; off < 32; off <<= 1) {
        int n = __shfl_up_sync(0xffffffffu, inc, off);
        if (lane >= off) inc += n;
    }
    float vzr = vz;                       // warp reduce zero-v sum
    #pragma unroll
    for (int off = 16; off; off >>= 1) vzr += __shfl_down_sync(0xffffffffu, vzr, off);
    if (lane == 31) soff[w] = inc;
    if (lane == 0)  sv[w]   = vzr;
    __syncthreads();
    if (t == 0) {                         // serial deterministic warp-offset scan
        int acc = 0; float vacc = 0.f; float mm = smax[0];
        #pragma unroll
        for (int i = 0; i < 32; i++) {
            int tmp = soff[i]; soff[i] = acc; acc += tmp;
            vacc += sv[i];
            mm = fmaxf(mm, smax[i]);
        }
        s_nnz = acc;
        s_P   = (acc + 63) & ~63;
        d_nnz[s]  = acc;
        d_P[s]    = s_P;
        d_S0[s]   = vacc * (1.0f / 4096.0f);
        d_qmax[s] = mm;
    }
    __syncthreads();
    int k = soff[w] + (inc - cnt);
    if (c0) { d_qnz[sb + k] = qv.x; d_idxnz[sb + k] = pos;     d_rank[sb + pos]     = k; k++; }
    if (c1) { d_qnz[sb + k] = qv.y; d_idxnz[sb + k] = pos + 1; d_rank[sb + pos + 1] = k; k++; }
    if (c2) { d_qnz[sb + k] = qv.z; d_idxnz[sb + k] = pos + 2; d_rank[sb + pos + 2] = k; k++; }
    if (c3) { d_qnz[sb + k] = qv.w; d_idxnz[sb + k] = pos + 3; d_rank[sb + pos + 3] = k; k++; }
    for (int i = s_nnz + t; i < s_P; i += 1024) {
        d_qnz[sb + i]  = 0.f;
        d_qanz[sb + i] = make_float2(0.f, 0.f);
    }
}

// ---------------------------------------------------------------------------
// K3: pass1 (R8 config): 1 row/lane, 32 rows/block, 8 warp-chunks.
// grid 1536 x 256: slice = blk>>7, rowgroup(32) = blk&127, chunk = warp
// ---------------------------------------------------------------------------
__global__ void k_pass1()
{
    int s = blockIdx.x >> 7;
    int g = blockIdx.x & 127;
    int nnz = d_nnz[s];
    if (g * 32 >= nnz) return;
    __shared__ float sq[4096];
    __shared__ float partZ[8][32];
    __shared__ float s_qmax;
    int t = threadIdx.x, w = t >> 5, lane = t & 31;
    int sb = s << 12;
    int P  = d_P[s];
    int P4 = P >> 2;

    float4* sq4 = (float4*)sq;
    const float4* gq4 = (const float4*)(d_qnz + sb);
    for (int j = t; j < P4; j += 256) sq4[j] = gq4[j];
    if (t == 0) s_qmax = d_qmax[s];
    __syncthreads();

    int k = g * 32 + lane;
    float qi   = (k < P) ? sq[k] : 0.f;
    float qln  = qi * L2E;
    float nmln = -qln * s_qmax;

    int P32 = P >> 5;                      // float4s per warp chunk
    const float4* p4 = (const float4*)sq + w * P32;
    float z0 = 0, z1 = 0, z2 = 0, z3 = 0;
    #pragma unroll 2
    for (int j4 = 0; j4 < P32; j4++) {
        float4 qq = p4[j4];                // warp-uniform broadcast
        z0 += ex2f_(fmaf(qln, qq.x, nmln));
        z1 += ex2f_(fmaf(qln, qq.y, nmln));
        z2 += ex2f_(fmaf(qln, qq.z, nmln));
        z3 += ex2f_(fmaf(qln, qq.w, nmln));
    }
    partZ[w][lane] = (z0 + z1) + (z2 + z3);
    __syncthreads();
    if (w == 0 && k < nnz) {
        float E = ex2f_(nmln);
        float Z = (((partZ[0][lane] + partZ[1][lane]) + (partZ[2][lane] + partZ[3][lane]))
                +  ((partZ[4][lane] + partZ[5][lane]) + (partZ[6][lane] + partZ[7][lane])))
                + (float)(4096 - P) * E;
        int row = d_idxnz[sb + k];
        float av = d_v[sb + row] / Z * E;
        d_qanz[sb + k] = make_float2(qln, av);
    }
}

// ---------------------------------------------------------------------------
// K4: pass2, 16 i-chunks, 2 rows/thread (256 rows/block). grid 3072 x 128
// slice = blk>>8; chunk = (blk&255)&15; rowgroup(256) = (blk&255)>>4
// Active blocks ~ 12 * 16 * ceil(nnz/256) ~= 1536 (R8-level occupancy)
// ---------------------------------------------------------------------------
__global__ void k_pass2()
{
    int s   = blockIdx.x >> 8;
    int rem = blockIdx.x & 255;
    int c   = rem & 15;
    int g   = rem >> 4;
    int nnz = d_nnz[s];
    if (g * 256 >= nnz) return;
    int P   = d_P[s];
    int P16 = P >> 4;                      // entries per chunk (mult of 4)
    __shared__ float2 sqa[256];            // up to 2 KB
    __shared__ float sanz[4];
    int t = threadIdx.x;
    int sb = s << 12;

    float4* s4 = (float4*)sqa;
    const float4* g4 = (const float4*)(d_qanz + sb + c * P16);
    int nf4 = P16 >> 1;                    // float4s in chunk (mult of 2)
    for (int j = t; j < nf4; j += 128) s4[j] = g4[j];
    __syncthreads();

    // Anz chunk partial (only g==0 blocks; data already in smem)
    if (g == 0) {
        int w = t >> 5, lane = t & 31;
        float a = 0.f;
        for (int i = t; i < P16; i += 128) a += sqa[i].y;
        #pragma unroll
        for (int off = 16; off; off >>= 1) a += __shfl_down_sync(0xffffffffu, a, off);
        if (lane == 0) sanz[w] = a;
    }

    int k0 = g * 256 + t;
    int k1 = k0 + 128;
    float qj0 = d_qnz[sb + ((k0 < nnz) ? k0 : 0)];
    float qj1 = d_qnz[sb + ((k1 < nnz) ? k1 : 0)];
    float a00 = 0, a01 = 0, a02 = 0, a03 = 0;
    float a10 = 0, a11 = 0, a12 = 0, a13 = 0;
    const float4* p4 = (const float4*)sqa;
    #pragma unroll 2
    for (int i4 = 0; i4 < nf4; i4 += 2) {
        float4 u  = p4[i4];                // {qln, a}, {qln, a}
        float4 ww = p4[i4 + 1];
        a00 = fmaf(u.y,  ex2f_(u.x  * qj0), a00);
        a10 = fmaf(u.y,  ex2f_(u.x  * qj1), a10);
        a01 = fmaf(u.w,  ex2f_(u.z  * qj0), a01);
        a11 = fmaf(u.w,  ex2f_(u.z  * qj1), a11);
        a02 = fmaf(ww.y, ex2f_(ww.x * qj0), a02);
        a12 = fmaf(ww.y, ex2f_(ww.x * qj1), a12);
        a03 = fmaf(ww.w, ex2f_(ww.z * qj0), a03);
        a13 = fmaf(ww.w, ex2f_(ww.z * qj1), a13);
    }
    if (k0 < nnz) d_ppart[c * NELEM + sb + k0] = (a00 + a01) + (a02 + a03);
    if (k1 < nnz) d_ppart[c * NELEM + sb + k1] = (a10 + a11) + (a12 + a13);

    if (g == 0) {
        __syncthreads();
        if (t == 0) d_AnzP[s][c] = (sanz[0] + sanz[1]) + (sanz[2] + sanz[3]);
    }
}

// ---------------------------------------------------------------------------
// K5: final — Datt inline + assemble Patt + residual. grid 64 x 256 over (c,hw)
// ---------------------------------------------------------------------------
__global__ void k_final(const float* __restrict__ x, const float* __restrict__ gama,
                        float* __restrict__ out)
{
    int tid = blockIdx.x * 256 + threadIdx.x;   // 0..16383
    int c = tid >> 12, hw = tid & 4095;
    int base = c * PERCH + hw;
    float gm = gama[0];

    float q0 = d_q[base], q1 = d_q[base + HW], q2 = d_q[base + 2 * HW];
    float v0 = d_v[base], v1 = d_v[base + HW], v2 = d_v[base + 2 * HW];

    // depth attention
    float qm = fmaxf(q0, fmaxf(q1, q2));
    float o0 = 0, o1 = 0, o2 = 0;
    {
        float ql = q0 * L2E, nm = -ql * qm;
        float e0 = ex2f_(fmaf(ql, q0, nm)), e1 = ex2f_(fmaf(ql, q1, nm)), e2 = ex2f_(fmaf(ql, q2, nm));
        float w_ = v0 / (e0 + e1 + e2);
        o0 = fmaf(w_, e0, o0); o1 = fmaf(w_, e1, o1); o2 = fmaf(w_, e2, o2);
    }
    {
        float ql = q1 * L2E, nm = -ql * qm;
        float e0 = ex2f_(fmaf(ql, q0, nm)), e1 = ex2f_(fmaf(ql, q1, nm)), e2 = ex2f_(fmaf(ql, q2, nm));
        float w_ = v1 / (e0 + e1 + e2);
        o0 = fmaf(w_, e0, o0); o1 = fmaf(w_, e1, o1); o2 = fmaf(w_, e2, o2);
    }
    {
        float ql = q2 * L2E, nm = -ql * qm;
        float e0 = ex2f_(fmaf(ql, q0, nm)), e1 = ex2f_(fmaf(ql, q1, nm)), e2 = ex2f_(fmaf(ql, q2, nm));
        float w_ = v2 / (e0 + e1 + e2);
        o0 = fmaf(w_, e0, o0); o1 = fmaf(w_, e1, o1); o2 = fmaf(w_, e2, o2);
    }

    float dat[3] = {o0, o1, o2};
    float qd[3]  = {q0, q1, q2};
    #pragma unroll
    for (int d = 0; d < 3; d++) {
        int s = c * 3 + d;
        int idx = base + d * HW;
        float patt;
        if (qd[d] > 0.f) {
            int b = (s << 12) + d_rank[idx];
            float p0 = 0.f;
            #pragma unroll
            for (int cc = 0; cc < 16; cc++) p0 += d_ppart[cc * NELEM + b];
            patt = p0;
        } else {
            float p0 = 0.f;
            #pragma unroll
            for (int cc = 0; cc < 16; cc++) p0 += d_AnzP[s][cc];
            patt = p0;
        }
        patt += d_S0[s];
        out[idx] = fmaf(gm, patt + dat[d], x[idx]);
    }
}

// ---------------------------------------------------------------------------
extern "C" void kernel_launch(void* const* d_in, const int* in_sizes, int n_in,
                              void* d_out, int out_size)
{
    const float* x    = (const float*)d_in[0];
    const float* W3   = (const float*)d_in[1];
    const float* b3   = (const float*)d_in[2];
    const float* g3   = (const float*)d_in[3];
    const float* be3  = (const float*)d_in[4];
    const float* W1   = (const float*)d_in[5];
    const float* b1   = (const float*)d_in[6];
    const float* g1   = (const float*)d_in[7];
    const float* be1  = (const float*)d_in[8];
    const float* gama = (const float*)d_in[9];
    float* out = (float*)d_out;

    k_conv <<<192,  256>>>(x, W3, b3, W1, b1);
    k_prep <<<12,  1024>>>(g3, be3, g1, be1);
    k_pass1<<<1536, 256>>>();
    k_pass2<<<3072, 128>>>();
    k_final<<<64,   256>>>(x, gama, out);
}

// round 11
// speedup vs baseline: 1.1524x; 1.0372x over previous
#include <cuda_runtime.h>

// Problem constants: N=1, C=4, D=3, H=W=64
#define NELEM 49152      // 4*3*64*64
#define HW    4096
#define PERCH 12288      // D*H*W per channel

__device__ float  d_vpre[NELEM];
__device__ float  d_kqpre[NELEM];
__device__ float  d_part[16 * 48];     // [quant(4)*chan(4)][48 block partials]
__device__ float  d_v[NELEM];
__device__ float  d_q[NELEM];
__device__ float  d_qmax[12];

// sparsity-compacted state (per slice of 4096)
__device__ int    d_nnz[12];
__device__ int    d_P[12];             // nnz padded up to multiple of 128
__device__ float  d_qnz[NELEM];        // compacted q values (padding = 0)
__device__ int    d_idxnz[NELEM];      // compacted k -> original pos
__device__ int    d_rank[NELEM];       // original pos -> compacted k (nz only)
__device__ float  d_S0[12];            // sum_{zero i} v_i / 4096
__device__ float  d_AnzP[12][16];      // per-chunk Anz partials
__device__ float2 d_qanz[NELEM];       // compacted {qln_i, a_i} (padding = {0,0})
__device__ float  d_ppart[16 * NELEM]; // pass2 chunk partials (compacted idx)

__device__ __forceinline__ float ex2f_(float x) {
    float y;
    asm("ex2.approx.f32 %0, %1;" : "=f"(y) : "f"(x));
    return y;
}

#define L2E 1.4426950408889634f

// ---------------------------------------------------------------------------
// K1: conv3x3x3 + bias and conv1x1x1 + bias; per-block stats partials
// ---------------------------------------------------------------------------
__global__ void k_conv(const float* __restrict__ x, const float* __restrict__ W3,
                       const float* __restrict__ b3, const float* __restrict__ W1,
                       const float* __restrict__ b1)
{
    __shared__ float sW3[432], sW1[16], sb3[4], sb1[4];
    int t = threadIdx.x;
    for (int i = t; i < 432; i += 256) sW3[i] = W3[i];
    if (t < 16)  sW1[t] = W1[t];
    if (t < 4) { sb3[t] = b3[t]; sb1[t] = b1[t]; }
    __syncthreads();

    int idx = blockIdx.x * 256 + t;
    int o  = idx / PERCH;
    int r  = idx % PERCH;
    int d  = r >> 12;
    int hw = r & 4095;
    int h  = hw >> 6;
    int w  = hw & 63;

    float acc3 = sb3[o], acc1 = sb1[o];
    #pragma unroll
    for (int i = 0; i < 4; i++) {
        const float* xi = x + i * PERCH;
        acc1 = fmaf(xi[(d << 12) + hw], sW1[o * 4 + i], acc1);
        const float* wk = sW3 + (o * 4 + i) * 27;
        #pragma unroll
        for (int kd = 0; kd < 3; kd++) {
            int zd = d + kd - 1;
            if (zd < 0 || zd > 2) continue;
            #pragma unroll
            for (int kh = 0; kh < 3; kh++) {
                int zh = h + kh - 1;
                if ((unsigned)zh > 63u) continue;
                #pragma unroll
                for (int kw = 0; kw < 3; kw++) {
                    int zw = w + kw - 1;
                    if ((unsigned)zw > 63u) continue;
                    acc3 = fmaf(xi[(zd << 12) + (zh << 6) + zw],
                                wk[kd * 9 + kh * 3 + kw], acc3);
                }
            }
        }
    }
    d_vpre[idx]  = acc3;
    d_kqpre[idx] = acc1;

    float v0 = acc3, v1 = acc3 * acc3, v2 = acc1, v3 = acc1 * acc1;
    #pragma unroll
    for (int off = 16; off; off >>= 1) {
        v0 += __shfl_down_sync(0xffffffffu, v0, off);
        v1 += __shfl_down_sync(0xffffffffu, v1, off);
        v2 += __shfl_down_sync(0xffffffffu, v2, off);
        v3 += __shfl_down_sync(0xffffffffu, v3, off);
    }
    __shared__ float sred[8][4];
    int wid = t >> 5, lane = t & 31;
    if (lane == 0) { sred[wid][0] = v0; sred[wid][1] = v1; sred[wid][2] = v2; sred[wid][3] = v3; }
    __syncthreads();
    if (t == 0) {
        float s0 = 0, s1 = 0, s2 = 0, s3 = 0;
        #pragma unroll
        for (int i = 0; i < 8; i++) { s0 += sred[i][0]; s1 += sred[i][1]; s2 += sred[i][2]; s3 += sred[i][3]; }
        int b2 = blockIdx.x % 48;
        d_part[(0 * 4 + o) * 48 + b2] = s0;
        d_part[(1 * 4 + o) * 48 + b2] = s1;
        d_part[(2 * 4 + o) * 48 + b2] = s2;
        d_part[(3 * 4 + o) * 48 + b2] = s3;
    }
}

// ---------------------------------------------------------------------------
// K2: fused stats + BN/ReLU + qmax + compaction. grid 12 x 1024 (block=slice)
// ---------------------------------------------------------------------------
__global__ void k_prep(const float* __restrict__ g3, const float* __restrict__ be3,
                       const float* __restrict__ g1, const float* __restrict__ be1)
{
    __shared__ float scoef[4];            // {sc3, sh3, sc1, sh1} for this channel
    __shared__ float ssum[4];
    __shared__ int   soff[32];
    __shared__ float sv[32];
    __shared__ float smax[32];
    __shared__ int   s_nnz, s_P;

    int s = blockIdx.x, t = threadIdx.x;
    int lane = t & 31, w = t >> 5;
    int c = s / 3;                        // channel
    int sb = s * 4096;

    // BN stats: threads 0..3 each reduce 48 partials for quantity q of channel c
    if (t < 4) {
        const float* p = d_part + (t * 4 + c) * 48;
        float a = 0.f;
        #pragma unroll
        for (int i = 0; i < 48; i++) a += p[i];
        ssum[t] = a;
    }
    __syncthreads();
    if (t == 0) {
        const float inv_n = 1.0f / 12288.0f;
        float m3  = ssum[0] * inv_n;
        float vr3 = ssum[1] * inv_n - m3 * m3;
        float sc3 = g3[c] * rsqrtf(vr3 + 1e-5f);
        float m1  = ssum[2] * inv_n;
        float vr1 = ssum[3] * inv_n - m1 * m1;
        float sc1 = g1[c] * rsqrtf(vr1 + 1e-5f);
        scoef[0] = sc3; scoef[1] = be3[c] - m3 * sc3;
        scoef[2] = sc1; scoef[3] = be1[c] - m1 * sc1;
        if (s == 0) {   // zero-init of Anz partials (pass2 overwrites when nnz>0)
            #pragma unroll
            for (int i = 0; i < 12; i++)
                #pragma unroll
                for (int jj = 0; jj < 16; jj++) d_AnzP[i][jj] = 0.f;
        }
    }
    __syncthreads();
    float sc3 = scoef[0], sh3 = scoef[1], sc1 = scoef[2], sh1 = scoef[3];

    // BN + ReLU on 4 consecutive elements
    int pos = t * 4;
    float4 pre3 = *(const float4*)(d_vpre  + sb + pos);
    float4 pre1 = *(const float4*)(d_kqpre + sb + pos);
    float4 vv, qv;
    vv.x = fmaxf(fmaf(pre3.x, sc3, sh3), 0.f);
    vv.y = fmaxf(fmaf(pre3.y, sc3, sh3), 0.f);
    vv.z = fmaxf(fmaf(pre3.z, sc3, sh3), 0.f);
    vv.w = fmaxf(fmaf(pre3.w, sc3, sh3), 0.f);
    qv.x = fmaxf(fmaf(pre1.x, sc1, sh1), 0.f);
    qv.y = fmaxf(fmaf(pre1.y, sc1, sh1), 0.f);
    qv.z = fmaxf(fmaf(pre1.z, sc1, sh1), 0.f);
    qv.w = fmaxf(fmaf(pre1.w, sc1, sh1), 0.f);
    *(float4*)(d_v + sb + pos) = vv;
    *(float4*)(d_q + sb + pos) = qv;

    // block qmax
    float m = fmaxf(fmaxf(qv.x, qv.y), fmaxf(qv.z, qv.w));
    #pragma unroll
    for (int off = 16; off; off >>= 1) m = fmaxf(m, __shfl_down_sync(0xffffffffu, m, off));
    if (lane == 0) smax[w] = m;

    // compaction flags + scans
    int c0 = qv.x > 0.f, c1 = qv.y > 0.f, c2 = qv.z > 0.f, c3 = qv.w > 0.f;
    int cnt = c0 + c1 + c2 + c3;
    float vz = (c0 ? 0.f : vv.x) + (c1 ? 0.f : vv.y)
             + (c2 ? 0.f : vv.z) + (c3 ? 0.f : vv.w);

    int inc = cnt;                        // warp inclusive scan
    #pragma unroll
    for (int off = 1; off < 32; off <<= 1) {
        int n = __shfl_up_sync(0xffffffffu, inc, off);
        if (lane >= off) inc += n;
    }
    float vzr = vz;                       // warp reduce zero-v sum
    #pragma unroll
    for (int off = 16; off; off >>= 1) vzr += __shfl_down_sync(0xffffffffu, vzr, off);
    if (lane == 31) soff[w] = inc;
    if (lane == 0)  sv[w]   = vzr;
    __syncthreads();
    if (t == 0) {                         // serial deterministic warp-offset scan
        int acc = 0; float vacc = 0.f; float mm = smax[0];
        #pragma unroll
        for (int i = 0; i < 32; i++) {
            int tmp = soff[i]; soff[i] = acc; acc += tmp;
            vacc += sv[i];
            mm = fmaxf(mm, smax[i]);
        }
        s_nnz = acc;
        s_P   = (acc + 127) & ~127;       // pad to multiple of 128
        d_nnz[s]  = acc;
        d_P[s]    = s_P;
        d_S0[s]   = vacc * (1.0f / 4096.0f);
        d_qmax[s] = mm;
    }
    __syncthreads();
    int k = soff[w] + (inc - cnt);
    if (c0) { d_qnz[sb + k] = qv.x; d_idxnz[sb + k] = pos;     d_rank[sb + pos]     = k; k++; }
    if (c1) { d_qnz[sb + k] = qv.y; d_idxnz[sb + k] = pos + 1; d_rank[sb + pos + 1] = k; k++; }
    if (c2) { d_qnz[sb + k] = qv.z; d_idxnz[sb + k] = pos + 2; d_rank[sb + pos + 2] = k; k++; }
    if (c3) { d_qnz[sb + k] = qv.w; d_idxnz[sb + k] = pos + 3; d_rank[sb + pos + 3] = k; k++; }
    for (int i = s_nnz + t; i < s_P; i += 1024) {
        d_qnz[sb + i]  = 0.f;
        d_qanz[sb + i] = make_float2(0.f, 0.f);
    }
}

// ---------------------------------------------------------------------------
// K3: pass1: 1 row/lane, 32 rows/block, 8 warp-chunks, 8-way unrolled inner.
// grid 1536 x 256: slice = blk>>7, rowgroup(32) = blk&127, chunk = warp
// ---------------------------------------------------------------------------
__global__ void k_pass1()
{
    int s = blockIdx.x >> 7;
    int g = blockIdx.x & 127;
    int nnz = d_nnz[s];
    if (g * 32 >= nnz) return;
    __shared__ float sq[4096];
    __shared__ float partZ[8][32];
    __shared__ float s_qmax;
    int t = threadIdx.x, w = t >> 5, lane = t & 31;
    int sb = s << 12;
    int P  = d_P[s];
    int P4 = P >> 2;

    float4* sq4 = (float4*)sq;
    const float4* gq4 = (const float4*)(d_qnz + sb);
    for (int j = t; j < P4; j += 256) sq4[j] = gq4[j];
    if (t == 0) s_qmax = d_qmax[s];
    __syncthreads();

    int k = g * 32 + lane;
    float qi   = (k < P) ? sq[k] : 0.f;
    float qln  = qi * L2E;
    float nmln = -qln * s_qmax;

    int P32 = P >> 5;                      // float4s per warp chunk (mult of 4)
    const float4* p4 = (const float4*)sq + w * P32;
    float z0 = 0, z1 = 0, z2 = 0, z3 = 0;
    float z4 = 0, z5 = 0, z6 = 0, z7 = 0;
    #pragma unroll 2
    for (int j4 = 0; j4 < P32; j4 += 2) {
        float4 qa = p4[j4];
        float4 qb = p4[j4 + 1];
        z0 += ex2f_(fmaf(qln, qa.x, nmln));
        z1 += ex2f_(fmaf(qln, qa.y, nmln));
        z2 += ex2f_(fmaf(qln, qa.z, nmln));
        z3 += ex2f_(fmaf(qln, qa.w, nmln));
        z4 += ex2f_(fmaf(qln, qb.x, nmln));
        z5 += ex2f_(fmaf(qln, qb.y, nmln));
        z6 += ex2f_(fmaf(qln, qb.z, nmln));
        z7 += ex2f_(fmaf(qln, qb.w, nmln));
    }
    partZ[w][lane] = ((z0 + z1) + (z2 + z3)) + ((z4 + z5) + (z6 + z7));
    __syncthreads();
    if (w == 0 && k < nnz) {
        float E = ex2f_(nmln);
        float Z = (((partZ[0][lane] + partZ[1][lane]) + (partZ[2][lane] + partZ[3][lane]))
                +  ((partZ[4][lane] + partZ[5][lane]) + (partZ[6][lane] + partZ[7][lane])))
                + (float)(4096 - P) * E;
        int row = d_idxnz[sb + k];
        float av = d_v[sb + row] / Z * E;
        d_qanz[sb + k] = make_float2(qln, av);
    }
}

// ---------------------------------------------------------------------------
// K4: pass2, 16 i-chunks, 1 row/thread (128 rows/block), 8 accumulators.
// grid 6144 x 128: slice = blk>>9; chunk = (blk&511)&15; rowgroup(128) = (blk&511)>>4
// Active blocks ~ 12 * 16 * ceil(nnz/128) ~= 3072 at nnz~2048
// ---------------------------------------------------------------------------
__global__ void k_pass2()
{
    int s   = blockIdx.x >> 9;
    int rem = blockIdx.x & 511;
    int c   = rem & 15;
    int g   = rem >> 4;                    // [0,32)
    int nnz = d_nnz[s];
    if (g * 128 >= nnz) return;
    int P   = d_P[s];
    int P16 = P >> 4;                      // entries per chunk (mult of 8)
    __shared__ float2 sqa[256];            // up to 2 KB
    __shared__ float sanz[4];
    int t = threadIdx.x;
    int sb = s << 12;

    float4* s4 = (float4*)sqa;
    const float4* g4 = (const float4*)(d_qanz + sb + c * P16);
    int nf4 = P16 >> 1;                    // float4s in chunk (mult of 4)
    for (int j = t; j < nf4; j += 128) s4[j] = g4[j];
    __syncthreads();

    // Anz chunk partial (only g==0 blocks; data already in smem)
    if (g == 0) {
        int w = t >> 5, lane = t & 31;
        float a = 0.f;
        for (int i = t; i < P16; i += 128) a += sqa[i].y;
        #pragma unroll
        for (int off = 16; off; off >>= 1) a += __shfl_down_sync(0xffffffffu, a, off);
        if (lane == 0) sanz[w] = a;
    }

    int k = g * 128 + t;
    float qj = d_qnz[sb + ((k < nnz) ? k : 0)];
    float a0 = 0, a1 = 0, a2 = 0, a3 = 0;
    float a4 = 0, a5 = 0, a6 = 0, a7 = 0;
    const float4* p = (const float4*)sqa;
    for (int i = 0; i < nf4; i += 4) {
        float4 u0 = p[i];
        float4 u1 = p[i + 1];
        float4 u2 = p[i + 2];
        float4 u3 = p[i + 3];
        a0 = fmaf(u0.y, ex2f_(u0.x * qj), a0);
        a1 = fmaf(u0.w, ex2f_(u0.z * qj), a1);
        a2 = fmaf(u1.y, ex2f_(u1.x * qj), a2);
        a3 = fmaf(u1.w, ex2f_(u1.z * qj), a3);
        a4 = fmaf(u2.y, ex2f_(u2.x * qj), a4);
        a5 = fmaf(u2.w, ex2f_(u2.z * qj), a5);
        a6 = fmaf(u3.y, ex2f_(u3.x * qj), a6);
        a7 = fmaf(u3.w, ex2f_(u3.z * qj), a7);
    }
    if (k < nnz)
        d_ppart[c * NELEM + sb + k] = ((a0 + a1) + (a2 + a3)) + ((a4 + a5) + (a6 + a7));

    if (g == 0) {
        __syncthreads();
        if (t == 0) d_AnzP[s][c] = (sanz[0] + sanz[1]) + (sanz[2] + sanz[3]);
    }
}

// ---------------------------------------------------------------------------
// K5: final — Datt inline + assemble Patt + residual. grid 64 x 256 over (c,hw)
// ---------------------------------------------------------------------------
__global__ void k_final(const float* __restrict__ x, const float* __restrict__ gama,
                        float* __restrict__ out)
{
    int tid = blockIdx.x * 256 + threadIdx.x;   // 0..16383
    int c = tid >> 12, hw = tid & 4095;
    int base = c * PERCH + hw;
    float gm = gama[0];

    float q0 = d_q[base], q1 = d_q[base + HW], q2 = d_q[base + 2 * HW];
    float v0 = d_v[base], v1 = d_v[base + HW], v2 = d_v[base + 2 * HW];

    // depth attention
    float qm = fmaxf(q0, fmaxf(q1, q2));
    float o0 = 0, o1 = 0, o2 = 0;
    {
        float ql = q0 * L2E, nm = -ql * qm;
        float e0 = ex2f_(fmaf(ql, q0, nm)), e1 = ex2f_(fmaf(ql, q1, nm)), e2 = ex2f_(fmaf(ql, q2, nm));
        float w_ = v0 / (e0 + e1 + e2);
        o0 = fmaf(w_, e0, o0); o1 = fmaf(w_, e1, o1); o2 = fmaf(w_, e2, o2);
    }
    {
        float ql = q1 * L2E, nm = -ql * qm;
        float e0 = ex2f_(fmaf(ql, q0, nm)), e1 = ex2f_(fmaf(ql, q1, nm)), e2 = ex2f_(fmaf(ql, q2, nm));
        float w_ = v1 / (e0 + e1 + e2);
        o0 = fmaf(w_, e0, o0); o1 = fmaf(w_, e1, o1); o2 = fmaf(w_, e2, o2);
    }
    {
        float ql = q2 * L2E, nm = -ql * qm;
        float e0 = ex2f_(fmaf(ql, q0, nm)), e1 = ex2f_(fmaf(ql, q1, nm)), e2 = ex2f_(fmaf(ql, q2, nm));
        float w_ = v2 / (e0 + e1 + e2);
        o0 = fmaf(w_, e0, o0); o1 = fmaf(w_, e1, o1); o2 = fmaf(w_, e2, o2);
    }

    float dat[3] = {o0, o1, o2};
    float qd[3]  = {q0, q1, q2};
    #pragma unroll
    for (int d = 0; d < 3; d++) {
        int s = c * 3 + d;
        int idx = base + d * HW;
        float patt;
        if (qd[d] > 0.f) {
            int b = (s << 12) + d_rank[idx];
            float p0 = 0.f;
            #pragma unroll
            for (int cc = 0; cc < 16; cc++) p0 += d_ppart[cc * NELEM + b];
            patt = p0;
        } else {
            float p0 = 0.f;
            #pragma unroll
            for (int cc = 0; cc < 16; cc++) p0 += d_AnzP[s][cc];
            patt = p0;
        }
        patt += d_S0[s];
        out[idx] = fmaf(gm, patt + dat[d], x[idx]);
    }
}

// ---------------------------------------------------------------------------
extern "C" void kernel_launch(void* const* d_in, const int* in_sizes, int n_in,
                              void* d_out, int out_size)
{
    const float* x    = (const float*)d_in[0];
    const float* W3   = (const float*)d_in[1];
    const float* b3   = (const float*)d_in[2];
    const float* g3   = (const float*)d_in[3];
    const float* be3  = (const float*)d_in[4];
    const float* W1   = (const float*)d_in[5];
    const float* b1   = (const float*)d_in[6];
    const float* g1   = (const float*)d_in[7];
    const float* be1  = (const float*)d_in[8];
    const float* gama = (const float*)d_in[9];
    float* out = (float*)d_out;

    k_conv <<<192,  256>>>(x, W3, b3, W1, b1);
    k_prep <<<12,  1024>>>(g3, be3, g1, be1);
    k_pass1<<<1536, 256>>>();
    k_pass2<<<6144, 128>>>();
    k_final<<<64,   256>>>(x, gama, out);
}